// round 12
// baseline (speedup 1.0000x reference)
#include <cuda_runtime.h>
#include <cuda_bf16.h>
#include <cstdint>

// ---------------- Problem sizes ----------------
#define TOKENS 4096
#define IN_F   8192
#define OUT_F  8192

#define KITERS   (IN_F / 64)            // 128
#define NTILES   (OUT_F / 128)          // 64
#define MTILES   (TOKENS / 128)         // 32

// ---- HMMA staging (R6 config: CTA 128x128, 8 warps, warp 32x64) ----
#define ROWB        144
#define A_STAGE_B   (128 * ROWB)        // 18432
#define STAGE_B     (2 * A_STAGE_B)     // 36864
#define NSTAGES_B   3
#define SMEM_H      (NSTAGES_B * STAGE_B)   // 110592

// ---- IMMA staging (R2 config: CTA 128x128, 8 warps, warp 32x64) ----
#define ROW_PAD     80
#define A_STAGE     (128 * ROW_PAD)
#define STAGE_I     (2 * A_STAGE)       // 20480
#define NSTAGES_I   4
#define SMEM_I      (NSTAGES_I * STAGE_I)   // 81920

#define SMEM_MIX    SMEM_H              // max of both

// ---------------- Scratch ----------------
__device__ __nv_bfloat16  g_Ab[(size_t)TOKENS * IN_F];   // 64 MB bf16 tiles
__device__ uint8_t        g_A8[(size_t)TOKENS * IN_F];   // 32 MB int8 tiles
__device__ __nv_bfloat16  g_Bb[(size_t)OUT_F  * IN_F];   // 128 MB (H-tiles only populated)
__device__ uint8_t        g_B8[(size_t)OUT_F  * IN_F];   // 64 MB (I-tiles only populated)
__device__ float          g_s[TOKENS];

// I-tile selector: 18 of every 64 n-tiles, Bresenham-interleaved
__device__ __forceinline__ bool is_imma_tile(int local) {
    return (((local + 1) * 18) >> 6) > ((local * 18) >> 6);
}

// ---------------- PTX helpers ----------------
__device__ __forceinline__ uint32_t smem_to_u32(const void* smem_ptr) {
    uint32_t addr;
    asm("{ .reg .u64 tmp; cvta.to.shared.u64 tmp, %1; cvt.u32.u64 %0, tmp; }"
        : "=r"(addr) : "l"(smem_ptr));
    return addr;
}

#define CP_ASYNC16(dst, src) \
    asm volatile("cp.async.cg.shared.global [%0], [%1], 16;" \
        :: "r"((uint32_t)(dst)), "l"(src) : "memory")
#define CP_COMMIT() asm volatile("cp.async.commit_group;" ::: "memory")
#define CP_WAIT2()  asm volatile("cp.async.wait_group 2;" ::: "memory")
#define CP_WAIT1()  asm volatile("cp.async.wait_group 1;" ::: "memory")

#define MMA_BF16(c, a, b0, b1) \
    asm volatile( \
        "mma.sync.aligned.m16n8k16.row.col.f32.bf16.bf16.f32 " \
        "{%0,%1,%2,%3}, {%4,%5,%6,%7}, {%8,%9}, {%0,%1,%2,%3};" \
        : "+f"((c)[0]), "+f"((c)[1]), "+f"((c)[2]), "+f"((c)[3]) \
        : "r"((a)[0]), "r"((a)[1]), "r"((a)[2]), "r"((a)[3]), \
          "r"(b0), "r"(b1))

#define MMA_S8(c, a, b0, b1) \
    asm volatile( \
        "mma.sync.aligned.m16n8k32.row.col.s32.s8.s8.s32 " \
        "{%0,%1,%2,%3}, {%4,%5,%6,%7}, {%8,%9}, {%0,%1,%2,%3};" \
        : "+r"((c)[0]), "+r"((c)[1]), "+r"((c)[2]), "+r"((c)[3]) \
        : "r"((a)[0]), "r"((a)[1]), "r"((a)[2]), "r"((a)[3]), \
          "r"(b0), "r"(b1))

#define LDMX4(r, addr) \
    asm volatile("ldmatrix.sync.aligned.m8n8.x4.shared.b16 {%0,%1,%2,%3}, [%4];" \
        : "=r"((r)[0]), "=r"((r)[1]), "=r"((r)[2]), "=r"((r)[3]) \
        : "r"((uint32_t)(addr)))

// ---------------- Kernel 1: quantize x -> bf16 tiles + int8 tiles + scale ----------------
__global__ void __launch_bounds__(256, 1) prep_x_kernel(const float* __restrict__ x) {
    int t = blockIdx.x;
    int tid = threadIdx.x;
    const float4* xr = reinterpret_cast<const float4*>(x + (size_t)t * IN_F) + tid * 8;

    float vv[32];
    float m = 0.0f;
#pragma unroll
    for (int j = 0; j < 8; j++) {
        float4 v4 = xr[j];
        vv[4 * j + 0] = v4.x; vv[4 * j + 1] = v4.y;
        vv[4 * j + 2] = v4.z; vv[4 * j + 3] = v4.w;
        m = fmaxf(m, fmaxf(fmaxf(fabsf(v4.x), fabsf(v4.y)), fmaxf(fabsf(v4.z), fabsf(v4.w))));
    }
#pragma unroll
    for (int o = 16; o > 0; o >>= 1)
        m = fmaxf(m, __shfl_xor_sync(0xFFFFFFFFu, m, o));

    __shared__ float wm_[8];
    __shared__ float sh_s;
    if ((tid & 31) == 0) wm_[tid >> 5] = m;
    __syncthreads();
    if (tid == 0) {
        float mm = wm_[0];
#pragma unroll
        for (int j = 1; j < 8; j++) mm = fmaxf(mm, wm_[j]);
        float s = 127.0f / fmaxf(mm, 1e-5f);
        g_s[t] = s;
        sh_s = s;
    }
    __syncthreads();
    float s = sh_s;

    int k0 = tid * 32;
    int kt = k0 >> 6;
    int c0 = k0 & 63;
    int r  = t & 127;
    int m_t = t >> 7;

    float q[32];
#pragma unroll
    for (int p = 0; p < 32; p++)
        q[p] = fminf(fmaxf(rintf(vv[p] * s), -128.0f), 127.0f);

    {   // bf16 tiled
        char* dst = reinterpret_cast<char*>(g_Ab) +
                    ((size_t)(m_t * KITERS + kt) << 14) + r * 128 + c0 * 2;
        uint32_t pk[16];
#pragma unroll
        for (int p = 0; p < 16; p++) {
            __nv_bfloat162 h = __floats2bfloat162_rn(q[2 * p], q[2 * p + 1]);
            pk[p] = *reinterpret_cast<uint32_t*>(&h);
        }
        uint4* d4 = reinterpret_cast<uint4*>(dst);
#pragma unroll
        for (int j = 0; j < 4; j++)
            d4[j] = make_uint4(pk[4 * j], pk[4 * j + 1], pk[4 * j + 2], pk[4 * j + 3]);
    }
    {   // int8 tiled
        uint8_t* dst = g_A8 + ((size_t)(m_t * KITERS + kt) << 13) + r * 64 + c0;
        uint32_t pk[8];
#pragma unroll
        for (int p = 0; p < 8; p++) {
            int q0 = (int)q[4 * p + 0], q1 = (int)q[4 * p + 1];
            int q2 = (int)q[4 * p + 2], q3 = (int)q[4 * p + 3];
            pk[p] = (uint32_t)(q0 & 0xFF) | ((uint32_t)(q1 & 0xFF) << 8) |
                    ((uint32_t)(q2 & 0xFF) << 16) | ((uint32_t)(q3 & 0xFF) << 24);
        }
        uint4* d4 = reinterpret_cast<uint4*>(dst);
        d4[0] = make_uint4(pk[0], pk[1], pk[2], pk[3]);
        d4[1] = make_uint4(pk[4], pk[5], pk[6], pk[7]);
    }
}

// ---------------- Kernel 2: weights -> bf16 tiles (H cols) or int8 tiles (I cols) ----------------
__global__ void __launch_bounds__(256, 1) prep_w_kernel(const int* __restrict__ w) {
    int n = blockIdx.x;
    int tid = threadIdx.x;
    int k0 = tid * 32;
    const int4* wr = reinterpret_cast<const int4*>(w + (size_t)n * IN_F + k0);

    int kt  = k0 >> 6;
    int c0  = k0 & 63;
    int n_t = n >> 7;
    int r   = n & 127;

    int vals[32];
#pragma unroll
    for (int p = 0; p < 8; p++) {
        int4 qq = wr[p];
        vals[4 * p + 0] = qq.x; vals[4 * p + 1] = qq.y;
        vals[4 * p + 2] = qq.z; vals[4 * p + 3] = qq.w;
    }

    if (is_imma_tile(n_t & 63)) {
        uint8_t* dst = g_B8 + ((size_t)(n_t * KITERS + kt) << 13) + r * 64 + c0;
        uint32_t pk[8];
#pragma unroll
        for (int p = 0; p < 8; p++)
            pk[p] = (uint32_t)(vals[4*p] & 0xFF) | ((uint32_t)(vals[4*p+1] & 0xFF) << 8) |
                    ((uint32_t)(vals[4*p+2] & 0xFF) << 16) | ((uint32_t)(vals[4*p+3] & 0xFF) << 24);
        uint4* d4 = reinterpret_cast<uint4*>(dst);
        d4[0] = make_uint4(pk[0], pk[1], pk[2], pk[3]);
        d4[1] = make_uint4(pk[4], pk[5], pk[6], pk[7]);
    } else {
        char* dst = reinterpret_cast<char*>(g_Bb) +
                    ((size_t)(n_t * KITERS + kt) << 14) + r * 128 + c0 * 2;
        uint32_t pk[16];
#pragma unroll
        for (int p = 0; p < 8; p++) {
            __nv_bfloat162 h0 = __floats2bfloat162_rn((float)vals[4*p],   (float)vals[4*p+1]);
            __nv_bfloat162 h1 = __floats2bfloat162_rn((float)vals[4*p+2], (float)vals[4*p+3]);
            pk[2 * p + 0] = *reinterpret_cast<uint32_t*>(&h0);
            pk[2 * p + 1] = *reinterpret_cast<uint32_t*>(&h1);
        }
        uint4* d4 = reinterpret_cast<uint4*>(dst);
#pragma unroll
        for (int j = 0; j < 4; j++)
            d4[j] = make_uint4(pk[4 * j], pk[4 * j + 1], pk[4 * j + 2], pk[4 * j + 3]);
    }
}

// ---------------- Kernel 3: heterogeneous GEMM (HMMA tiles + IMMA tiles) ----------------
// 2048 blocks, 256 threads. Per block: n_t = bx & 63, m_t = bx >> 6; path by tile type.
__global__ void __launch_bounds__(256, 2) gemm_mix_kernel(
    const float* __restrict__ wscale,
    const float* __restrict__ bias,
    float* __restrict__ out
) {
    extern __shared__ char smem[];
    uint32_t sb = smem_to_u32(smem);
    int tid = threadIdx.x, wid = tid >> 5, lane = tid & 31;
    int wm = wid & 3, wn = wid >> 2;
    int g = lane >> 2, tig = lane & 3;

    int bx  = blockIdx.x;
    int n_t = bx & 63;
    int m_t = bx >> 6;
    float wsc = wscale[0];

    if (!is_imma_tile(n_t)) {
        // ================= HMMA path (R6 body) =================
        const char* Ag = reinterpret_cast<const char*>(g_Ab) + ((size_t)(m_t * KITERS) << 14);
        const char* Bg = reinterpret_cast<const char*>(g_Bb) + ((size_t)(n_t * KITERS) << 14);

        int quad = lane >> 3, lr = lane & 7;
        uint32_t a_off = (uint32_t)((wm * 32 + (quad & 1) * 8 + lr) * ROWB + (quad >> 1) * 16);
        uint32_t b_off = (uint32_t)(A_STAGE_B + (wn * 64 + (quad >> 1) * 8 + lr) * ROWB + (quad & 1) * 16);

        float acc[2][8][4];
#pragma unroll
        for (int mb = 0; mb < 2; mb++)
#pragma unroll
            for (int nb = 0; nb < 8; nb++)
#pragma unroll
                for (int i = 0; i < 4; i++) acc[mb][nb][i] = 0.0f;

#pragma unroll
        for (int p = 0; p < NSTAGES_B - 1; p++) {
            uint32_t dstA = sb + p * STAGE_B;
            uint32_t dstB = dstA + A_STAGE_B;
            const char* srcA = Ag + ((size_t)p << 14);
            const char* srcB = Bg + ((size_t)p << 14);
#pragma unroll
            for (int j = 0; j < 4; j++) {
                int idx = j * 256 + tid, r = idx >> 3, c = idx & 7;
                CP_ASYNC16(dstA + r * ROWB + c * 16, srcA + idx * 16);
                CP_ASYNC16(dstB + r * ROWB + c * 16, srcB + idx * 16);
            }
            CP_COMMIT();
        }

        for (int kt = 0; kt < KITERS; kt++) {
            CP_WAIT1();
            __syncthreads();
            int kn = kt + NSTAGES_B - 1;
            if (kn < KITERS) {
                int sn = kn % NSTAGES_B;
                uint32_t dstA = sb + sn * STAGE_B;
                uint32_t dstB = dstA + A_STAGE_B;
                const char* srcA = Ag + ((size_t)kn << 14);
                const char* srcB = Bg + ((size_t)kn << 14);
#pragma unroll
                for (int j = 0; j < 4; j++) {
                    int idx = j * 256 + tid, r = idx >> 3, c = idx & 7;
                    CP_ASYNC16(dstA + r * ROWB + c * 16, srcA + idx * 16);
                    CP_ASYNC16(dstB + r * ROWB + c * 16, srcB + idx * 16);
                }
            }
            CP_COMMIT();

            uint32_t stb = sb + (kt % NSTAGES_B) * STAGE_B;
#pragma unroll
            for (int ks = 0; ks < 4; ks++) {
                uint32_t ko = (uint32_t)(ks * 32);
                uint32_t a[2][4];
                LDMX4(a[0], stb + a_off + ko);
                LDMX4(a[1], stb + a_off + 16 * ROWB + ko);
#pragma unroll
                for (int nbp = 0; nbp < 4; nbp++) {
                    uint32_t b[4];
                    LDMX4(b, stb + b_off + nbp * 16 * ROWB + ko);
                    MMA_BF16(acc[0][2 * nbp + 0], a[0], b[0], b[1]);
                    MMA_BF16(acc[1][2 * nbp + 0], a[1], b[0], b[1]);
                    MMA_BF16(acc[0][2 * nbp + 1], a[0], b[2], b[3]);
                    MMA_BF16(acc[1][2 * nbp + 1], a[1], b[2], b[3]);
                }
            }
        }

#pragma unroll
        for (int mb = 0; mb < 2; mb++) {
            int r_a = m_t * 128 + wm * 32 + mb * 16 + g;
            int r_b = r_a + 8;
            float sca = 1.0f / (g_s[r_a] * wsc);
            float scb = 1.0f / (g_s[r_b] * wsc);
            float* outa = out + (size_t)r_a * OUT_F;
            float* outb = out + (size_t)r_b * OUT_F;
#pragma unroll
            for (int nb = 0; nb < 8; nb++) {
                int col = n_t * 128 + wn * 64 + nb * 8 + tig * 2;
                float2 bi = *reinterpret_cast<const float2*>(bias + col);
                float2 o;
                o.x = acc[mb][nb][0] * sca + bi.x;
                o.y = acc[mb][nb][1] * sca + bi.y;
                *reinterpret_cast<float2*>(outa + col) = o;
                o.x = acc[mb][nb][2] * scb + bi.x;
                o.y = acc[mb][nb][3] * scb + bi.y;
                *reinterpret_cast<float2*>(outb + col) = o;
            }
        }
    } else {
        // ================= IMMA path (R2 body, ALU-pipe) =================
        const uint8_t* Ag = g_A8 + ((size_t)(m_t * KITERS) << 13);
        const uint8_t* Bg = g_B8 + ((size_t)(n_t * KITERS) << 13);
        int idxs[2] = { tid, tid + 256 };

        int acc[2][8][4];
#pragma unroll
        for (int mb = 0; mb < 2; mb++)
#pragma unroll
            for (int nb = 0; nb < 8; nb++)
#pragma unroll
                for (int i = 0; i < 4; i++) acc[mb][nb][i] = 0;

#pragma unroll
        for (int p = 0; p < NSTAGES_I - 1; p++) {
            uint32_t dstA = sb + p * STAGE_I;
            uint32_t dstB = dstA + A_STAGE;
            const uint8_t* srcA = Ag + ((size_t)p << 13);
            const uint8_t* srcB = Bg + ((size_t)p << 13);
#pragma unroll
            for (int j = 0; j < 2; j++) {
                int idx = idxs[j], r = idx >> 2, c = idx & 3;
                CP_ASYNC16(dstA + r * ROW_PAD + c * 16, srcA + idx * 16);
                CP_ASYNC16(dstB + r * ROW_PAD + c * 16, srcB + idx * 16);
            }
            CP_COMMIT();
        }

        for (int kt = 0; kt < KITERS; kt++) {
            CP_WAIT2();
            __syncthreads();
            int kn = kt + NSTAGES_I - 1;
            if (kn < KITERS) {
                int sn = kn & (NSTAGES_I - 1);
                uint32_t dstA = sb + sn * STAGE_I;
                uint32_t dstB = dstA + A_STAGE;
                const uint8_t* srcA = Ag + ((size_t)kn << 13);
                const uint8_t* srcB = Bg + ((size_t)kn << 13);
#pragma unroll
                for (int j = 0; j < 2; j++) {
                    int idx = idxs[j], r = idx >> 2, c = idx & 3;
                    CP_ASYNC16(dstA + r * ROW_PAD + c * 16, srcA + idx * 16);
                    CP_ASYNC16(dstB + r * ROW_PAD + c * 16, srcB + idx * 16);
                }
            }
            CP_COMMIT();

            int s = kt & (NSTAGES_I - 1);
            const char* As = smem + s * STAGE_I;
            const char* Bs = As + A_STAGE;
#pragma unroll
            for (int ks = 0; ks < 2; ks++) {
                uint32_t a[2][4];
#pragma unroll
                for (int mb = 0; mb < 2; mb++) {
                    const char* ab = As + (wm * 32 + mb * 16 + g) * ROW_PAD + ks * 32 + tig * 4;
                    a[mb][0] = *reinterpret_cast<const uint32_t*>(ab);
                    a[mb][1] = *reinterpret_cast<const uint32_t*>(ab + 8 * ROW_PAD);
                    a[mb][2] = *reinterpret_cast<const uint32_t*>(ab + 16);
                    a[mb][3] = *reinterpret_cast<const uint32_t*>(ab + 8 * ROW_PAD + 16);
                }
#pragma unroll
                for (int nb = 0; nb < 8; nb++) {
                    const char* bb = Bs + (wn * 64 + nb * 8 + g) * ROW_PAD + ks * 32 + tig * 4;
                    uint32_t b0 = *reinterpret_cast<const uint32_t*>(bb);
                    uint32_t b1 = *reinterpret_cast<const uint32_t*>(bb + 16);
                    MMA_S8(acc[0][nb], a[0], b0, b1);
                    MMA_S8(acc[1][nb], a[1], b0, b1);
                }
            }
        }

#pragma unroll
        for (int mb = 0; mb < 2; mb++) {
            int r_a = m_t * 128 + wm * 32 + mb * 16 + g;
            int r_b = r_a + 8;
            float sca = 1.0f / (g_s[r_a] * wsc);
            float scb = 1.0f / (g_s[r_b] * wsc);
            float* outa = out + (size_t)r_a * OUT_F;
            float* outb = out + (size_t)r_b * OUT_F;
#pragma unroll
            for (int nb = 0; nb < 8; nb++) {
                int col = n_t * 128 + wn * 64 + nb * 8 + tig * 2;
                float2 bi = *reinterpret_cast<const float2*>(bias + col);
                float2 o;
                o.x = (float)acc[mb][nb][0] * sca + bi.x;
                o.y = (float)acc[mb][nb][1] * sca + bi.y;
                *reinterpret_cast<float2*>(outa + col) = o;
                o.x = (float)acc[mb][nb][2] * scb + bi.x;
                o.y = (float)acc[mb][nb][3] * scb + bi.y;
                *reinterpret_cast<float2*>(outb + col) = o;
            }
        }
    }
}

// ---------------- Launch ----------------
extern "C" void kernel_launch(void* const* d_in, const int* in_sizes, int n_in,
                              void* d_out, int out_size) {
    const float* x      = (const float*)d_in[0];
    const int*   weight = (const int*)d_in[1];
    const float* wscale = (const float*)d_in[2];
    const float* bias   = (const float*)d_in[3];
    float*       out    = (float*)d_out;

    prep_x_kernel<<<TOKENS, 256>>>(x);
    prep_w_kernel<<<OUT_F, 256>>>(weight);

    cudaFuncSetAttribute(gemm_mix_kernel, cudaFuncAttributeMaxDynamicSharedMemorySize, SMEM_MIX);
    gemm_mix_kernel<<<MTILES * 64, 256, SMEM_MIX>>>(wscale, bias, out);
}

// round 13
// speedup vs baseline: 1.5845x; 1.5845x over previous
#include <cuda_runtime.h>
#include <cuda_bf16.h>
#include <cstdint>

// ---------------- Problem sizes ----------------
#define TOKENS 4096
#define IN_F   8192
#define OUT_F  8192

#define KITERS   (IN_F / 64)            // 128
#define NTILES   (OUT_F / 128)          // 64
#define MTILES   (TOKENS / 128)         // 32

// ---- bf16 GEMM staging: CTA 128x128, 4 warps (64x64 each), 2 CTAs/SM ----
#define ROWB        144                 // 128B data + 16B pad (bank stride 36 -> conflict-free)
#define A_STAGE_B   (128 * ROWB)        // 18432
#define STAGE_B     (2 * A_STAGE_B)     // 36864
#define NSTAGES_B   3
#define GEMM_SMEM_B (NSTAGES_B * STAGE_B)   // 110592 -> 2 CTAs/SM (221 KB)

// ---------------- Scratch ----------------
__device__ __nv_bfloat16  g_Ab[(size_t)TOKENS * IN_F];   // 64 MB, tiled [m_t][kt][128][64]
__device__ __nv_bfloat16  g_Bb[(size_t)OUT_F  * IN_F];   // 128 MB, tiled [n_t][kt][128][64]
__device__ float          g_s[TOKENS];

// ---------------- PTX helpers ----------------
__device__ __forceinline__ uint32_t smem_to_u32(const void* smem_ptr) {
    uint32_t addr;
    asm("{ .reg .u64 tmp; cvta.to.shared.u64 tmp, %1; cvt.u32.u64 %0, tmp; }"
        : "=r"(addr) : "l"(smem_ptr));
    return addr;
}

#define CP_ASYNC16(dst, src) \
    asm volatile("cp.async.cg.shared.global [%0], [%1], 16;" \
        :: "r"((uint32_t)(dst)), "l"(src) : "memory")
#define CP_COMMIT() asm volatile("cp.async.commit_group;" ::: "memory")
#define CP_WAIT1()  asm volatile("cp.async.wait_group 1;" ::: "memory")

#define MMA_BF16(c, a, b0, b1) \
    asm volatile( \
        "mma.sync.aligned.m16n8k16.row.col.f32.bf16.bf16.f32 " \
        "{%0,%1,%2,%3}, {%4,%5,%6,%7}, {%8,%9}, {%0,%1,%2,%3};" \
        : "+f"((c)[0]), "+f"((c)[1]), "+f"((c)[2]), "+f"((c)[3]) \
        : "r"((a)[0]), "r"((a)[1]), "r"((a)[2]), "r"((a)[3]), \
          "r"(b0), "r"(b1))

#define LDMX4(r, addr) \
    asm volatile("ldmatrix.sync.aligned.m8n8.x4.shared.b16 {%0,%1,%2,%3}, [%4];" \
        : "=r"((r)[0]), "=r"((r)[1]), "=r"((r)[2]), "=r"((r)[3]) \
        : "r"((uint32_t)(addr)))

// ---------------- Kernel 1: merged prep (x-quant blocks + weight-convert blocks) ----------------
// Blocks [0, TOKENS): quantize one token row -> bf16 tile + scale.
// Blocks [TOKENS, TOKENS+OUT_F): convert one weight row -> bf16 tile.
__global__ void __launch_bounds__(256, 1) prep_kernel(
    const float* __restrict__ x, const int* __restrict__ w
) {
    int b = blockIdx.x;
    int tid = threadIdx.x;
    int k0 = tid * 32;
    int kt = k0 >> 6;
    int c0 = k0 & 63;

    if (b < TOKENS) {
        int t = b;
        const float4* xr = reinterpret_cast<const float4*>(x + (size_t)t * IN_F) + tid * 8;

        float vv[32];
        float m = 0.0f;
#pragma unroll
        for (int j = 0; j < 8; j++) {
            float4 v4 = xr[j];
            vv[4 * j + 0] = v4.x; vv[4 * j + 1] = v4.y;
            vv[4 * j + 2] = v4.z; vv[4 * j + 3] = v4.w;
            m = fmaxf(m, fmaxf(fmaxf(fabsf(v4.x), fabsf(v4.y)), fmaxf(fabsf(v4.z), fabsf(v4.w))));
        }
#pragma unroll
        for (int o = 16; o > 0; o >>= 1)
            m = fmaxf(m, __shfl_xor_sync(0xFFFFFFFFu, m, o));

        __shared__ float wm_[8];
        __shared__ float sh_s;
        if ((tid & 31) == 0) wm_[tid >> 5] = m;
        __syncthreads();
        if (tid == 0) {
            float mm = wm_[0];
#pragma unroll
            for (int j = 1; j < 8; j++) mm = fmaxf(mm, wm_[j]);
            float s = 127.0f / fmaxf(mm, 1e-5f);
            g_s[t] = s;
            sh_s = s;
        }
        __syncthreads();
        float s = sh_s;

        int r   = t & 127;
        int m_t = t >> 7;
        char* dst = reinterpret_cast<char*>(g_Ab) +
                    ((size_t)(m_t * KITERS + kt) << 14) + r * 128 + c0 * 2;
        uint32_t pk[16];
#pragma unroll
        for (int p = 0; p < 16; p++) {
            float qa = fminf(fmaxf(rintf(vv[2 * p + 0] * s), -128.0f), 127.0f);
            float qb = fminf(fmaxf(rintf(vv[2 * p + 1] * s), -128.0f), 127.0f);
            __nv_bfloat162 h = __floats2bfloat162_rn(qa, qb);
            pk[p] = *reinterpret_cast<uint32_t*>(&h);
        }
        uint4* d4 = reinterpret_cast<uint4*>(dst);
#pragma unroll
        for (int j = 0; j < 4; j++)
            d4[j] = make_uint4(pk[4 * j], pk[4 * j + 1], pk[4 * j + 2], pk[4 * j + 3]);
    } else {
        int n = b - TOKENS;
        const int4* wr = reinterpret_cast<const int4*>(w + (size_t)n * IN_F + k0);

        int n_t = n >> 7;
        int r   = n & 127;
        char* dst = reinterpret_cast<char*>(g_Bb) +
                    ((size_t)(n_t * KITERS + kt) << 14) + r * 128 + c0 * 2;
        uint32_t pk[16];
#pragma unroll
        for (int p = 0; p < 8; p++) {
            int4 q = wr[p];
            __nv_bfloat162 h0 = __floats2bfloat162_rn((float)q.x, (float)q.y);
            __nv_bfloat162 h1 = __floats2bfloat162_rn((float)q.z, (float)q.w);
            pk[2 * p + 0] = *reinterpret_cast<uint32_t*>(&h0);
            pk[2 * p + 1] = *reinterpret_cast<uint32_t*>(&h1);
        }
        uint4* d4 = reinterpret_cast<uint4*>(dst);
#pragma unroll
        for (int j = 0; j < 4; j++)
            d4[j] = make_uint4(pk[4 * j], pk[4 * j + 1], pk[4 * j + 2], pk[4 * j + 3]);
    }
}

// ---------------- Kernel 2: bf16 HMMA GEMM, CTA 128x128, 4 warps (64x64 each) ----------------
// 2 CTAs/SM. wm = wid&1 (64 M-rows), wn = wid>>1 (64 N-cols).  [R11 body, verified]
__global__ void __launch_bounds__(128, 1) gemm_bf_kernel(
    const float* __restrict__ wscale,
    const float* __restrict__ bias,
    float* __restrict__ out
) {
    extern __shared__ char smem[];
    uint32_t sb = smem_to_u32(smem);
    int tid = threadIdx.x, wid = tid >> 5, lane = tid & 31;
    int wm = wid & 1, wn = wid >> 1;
    int g = lane >> 2, tig = lane & 3;

    int n_t = blockIdx.x;   // 0..63
    int m_t = blockIdx.y;   // 0..31

    const char* Ag = reinterpret_cast<const char*>(g_Ab) + ((size_t)(m_t * KITERS) << 14);
    const char* Bg = reinterpret_cast<const char*>(g_Bb) + ((size_t)(n_t * KITERS) << 14);

    int quad = lane >> 3, lr = lane & 7;
    uint32_t a_off = (uint32_t)((wm * 64 + (quad & 1) * 8 + lr) * ROWB + (quad >> 1) * 16);
    uint32_t b_off = (uint32_t)(A_STAGE_B + (wn * 64 + (quad >> 1) * 8 + lr) * ROWB + (quad & 1) * 16);

    float acc[4][8][4];
#pragma unroll
    for (int mb = 0; mb < 4; mb++)
#pragma unroll
        for (int nb = 0; nb < 8; nb++)
#pragma unroll
            for (int i = 0; i < 4; i++) acc[mb][nb][i] = 0.0f;

#pragma unroll
    for (int p = 0; p < NSTAGES_B - 1; p++) {
        uint32_t dstA = sb + p * STAGE_B;
        uint32_t dstB = dstA + A_STAGE_B;
        const char* srcA = Ag + ((size_t)p << 14);
        const char* srcB = Bg + ((size_t)p << 14);
#pragma unroll
        for (int j = 0; j < 8; j++) {
            int idx = j * 128 + tid, r = idx >> 3, c = idx & 7;
            CP_ASYNC16(dstA + r * ROWB + c * 16, srcA + idx * 16);
            CP_ASYNC16(dstB + r * ROWB + c * 16, srcB + idx * 16);
        }
        CP_COMMIT();
    }

    for (int kt = 0; kt < KITERS; kt++) {
        CP_WAIT1();
        __syncthreads();
        int kn = kt + NSTAGES_B - 1;
        if (kn < KITERS) {
            int sn = kn % NSTAGES_B;
            uint32_t dstA = sb + sn * STAGE_B;
            uint32_t dstB = dstA + A_STAGE_B;
            const char* srcA = Ag + ((size_t)kn << 14);
            const char* srcB = Bg + ((size_t)kn << 14);
#pragma unroll
            for (int j = 0; j < 8; j++) {
                int idx = j * 128 + tid, r = idx >> 3, c = idx & 7;
                CP_ASYNC16(dstA + r * ROWB + c * 16, srcA + idx * 16);
                CP_ASYNC16(dstB + r * ROWB + c * 16, srcB + idx * 16);
            }
        }
        CP_COMMIT();

        uint32_t stb = sb + (kt % NSTAGES_B) * STAGE_B;
#pragma unroll
        for (int ks = 0; ks < 4; ks++) {           // 4 x k16 per 64-elem stage
            uint32_t ko = (uint32_t)(ks * 32);
            uint32_t a[4][4];
#pragma unroll
            for (int mb = 0; mb < 4; mb++)
                LDMX4(a[mb], stb + a_off + mb * 16 * ROWB + ko);
#pragma unroll
            for (int nbp = 0; nbp < 4; nbp++) {    // each covers 2 n-blocks
                uint32_t b[4];
                LDMX4(b, stb + b_off + nbp * 16 * ROWB + ko);
#pragma unroll
                for (int mb = 0; mb < 4; mb++) {
                    MMA_BF16(acc[mb][2 * nbp + 0], a[mb], b[0], b[1]);
                    MMA_BF16(acc[mb][2 * nbp + 1], a[mb], b[2], b[3]);
                }
            }
        }
    }

    // ---- epilogue: dequant + bias ----
    float wsc = wscale[0];
#pragma unroll
    for (int mb = 0; mb < 4; mb++) {
        int r_a = m_t * 128 + wm * 64 + mb * 16 + g;
        int r_b = r_a + 8;
        float sca = 1.0f / (g_s[r_a] * wsc);
        float scb = 1.0f / (g_s[r_b] * wsc);
        float* outa = out + (size_t)r_a * OUT_F;
        float* outb = out + (size_t)r_b * OUT_F;
#pragma unroll
        for (int nb = 0; nb < 8; nb++) {
            int col = n_t * 128 + wn * 64 + nb * 8 + tig * 2;
            float2 bi = *reinterpret_cast<const float2*>(bias + col);
            float2 o;
            o.x = acc[mb][nb][0] * sca + bi.x;
            o.y = acc[mb][nb][1] * sca + bi.y;
            *reinterpret_cast<float2*>(outa + col) = o;
            o.x = acc[mb][nb][2] * scb + bi.x;
            o.y = acc[mb][nb][3] * scb + bi.y;
            *reinterpret_cast<float2*>(outb + col) = o;
        }
    }
}

// ---------------- Launch ----------------
extern "C" void kernel_launch(void* const* d_in, const int* in_sizes, int n_in,
                              void* d_out, int out_size) {
    const float* x      = (const float*)d_in[0];
    const int*   weight = (const int*)d_in[1];
    const float* wscale = (const float*)d_in[2];
    const float* bias   = (const float*)d_in[3];
    float*       out    = (float*)d_out;

    prep_kernel<<<TOKENS + OUT_F, 256>>>(x, weight);

    cudaFuncSetAttribute(gemm_bf_kernel, cudaFuncAttributeMaxDynamicSharedMemorySize, GEMM_SMEM_B);
    gemm_bf_kernel<<<dim3(NTILES, MTILES), 128, GEMM_SMEM_B>>>(wscale, bias, out);
}